// round 12
// baseline (speedup 1.0000x reference)
#include <cuda_runtime.h>
#include <math.h>

#define BB 16
#define SS 8192
#define DD 512
#define SCALE_F 0.125
#define PAD 33   // smem row pad: conflict-free scalar reads

// ---------------- scratch (__device__ globals; no allocations allowed) --------
__device__ double        g_hs[BB * DD];        // sum of normalized tokens (fp64)
__device__ double        g_t[BB * DD];         // t = Wk @ hs (fp64)
__device__ double        g_vpart[BB * 8 * DD]; // stage2 partials (fp64)
__device__ float         g_invnorm[BB * SS];   // 1/max(||hidden_row||, 1e-12)
__device__ unsigned char g_hard[BB * SS];      // boundary bits
__device__ int           g_keptidx[BB * SS];   // compacted kept indices per batch
__device__ int           g_count[BB];          // kept counts

// ---- df64 helpers: exact product + Knuth two-sum compensated accumulation ----
__device__ __forceinline__ void df_acc(float x, float hi, float lo,
                                       float& s, float& c) {
    float p_hi = x * hi;
    float p_lo = fmaf(x, hi, -p_hi);
    p_lo = fmaf(x, lo, p_lo);
    float t  = s + p_hi;
    float bv = t - s;
    float e  = (s - (t - bv)) + (p_hi - bv);
    s = t;
    c += e + p_lo;
}

// ---------------- kernel 0: zero hs ------------------------------------------
__global__ void zero_hs_kernel() {
    int i = blockIdx.x * blockDim.x + threadIdx.x;
    if (i < BB * DD) g_hs[i] = 0.0;
}

// ---------------- kernel 1: fused invnorm + hs, SINGLE pass over hidden -------
// grid = 8192 (512 per batch), 256 thr (8 warps), 16 tokens/block (2/warp).
// smem ~34.5KB, NO register cap (min-blocks 2) -> ~4 blocks/SM, 32 warps/SM.
// Phase A: stream rows global->SMEM tile + fp32 sumsq partials
// Phase B: lanes 0-1 tree-reduce one token each -> invnorm
// Phase C: re-read rows from SMEM, accumulate hs; tile reused as combine buffer.
__global__ void __launch_bounds__(256, 2) normhs_kernel(const float* __restrict__ hidden) {
    extern __shared__ float dyn[];
    float* tile  = dyn;                       // 16 * 512 (reused as wacc later)
    float* part  = dyn + 16 * DD;             // 16 * PAD
    float* shinv = part + 16 * PAD;           // 16

    int warp = threadIdx.x >> 5;
    int lane = threadIdx.x & 31;
    int batch = blockIdx.x >> 9;                     // 512 blocks per batch
    int tokb  = (blockIdx.x & 511) * 16;             // block token base
    int tok0  = tokb + warp * 2;                     // warp token base

    const float4* base = (const float4*)(hidden + (size_t)batch * SS * DD);

    // ---- phase A: global -> sumsq partials + SMEM tile (pure stream) ----
#pragma unroll
    for (int t = 0; t < 2; t++) {
        int r = warp * 2 + t;
        const float4* row = base + (size_t)(tok0 + t) * (DD / 4);
        float4* trow = (float4*)(tile + r * DD);
        float4 x0 = row[lane];
        float4 x1 = row[lane + 32];
        float4 x2 = row[lane + 64];
        float4 x3 = row[lane + 96];
        float s0 = 0.f, s1 = 0.f, s2 = 0.f, s3 = 0.f;
        s0 = fmaf(x0.x, x0.x, s0); s1 = fmaf(x0.y, x0.y, s1);
        s2 = fmaf(x0.z, x0.z, s2); s3 = fmaf(x0.w, x0.w, s3);
        s0 = fmaf(x1.x, x1.x, s0); s1 = fmaf(x1.y, x1.y, s1);
        s2 = fmaf(x1.z, x1.z, s2); s3 = fmaf(x1.w, x1.w, s3);
        s0 = fmaf(x2.x, x2.x, s0); s1 = fmaf(x2.y, x2.y, s1);
        s2 = fmaf(x2.z, x2.z, s2); s3 = fmaf(x2.w, x2.w, s3);
        s0 = fmaf(x3.x, x3.x, s0); s1 = fmaf(x3.y, x3.y, s1);
        s2 = fmaf(x3.z, x3.z, s2); s3 = fmaf(x3.w, x3.w, s3);
        trow[lane]      = x0;
        trow[lane + 32] = x1;
        trow[lane + 64] = x2;
        trow[lane + 96] = x3;
        part[r * PAD + lane] = (s0 + s1) + (s2 + s3);
    }
    __syncwarp();

    // ---- phase B: lanes 0-1 reduce one token each (fp32 pairwise tree) ----
    if (lane < 2) {
        int r = warp * 2 + lane;
        const float* p = &part[r * PAD];
        float q[32];
#pragma unroll
        for (int j = 0; j < 32; j++) q[j] = p[j];
#pragma unroll
        for (int w = 16; w > 0; w >>= 1)
#pragma unroll
            for (int j = 0; j < 32; j++) if (j < w) q[j] = q[j] + q[j + w];
        float iv = 1.0f / fmaxf(sqrtf(q[0]), 1e-12f);
        g_invnorm[batch * SS + tok0 + lane] = iv;
        shinv[r] = iv;
    }
    __syncwarp();

    // ---- phase C: re-read rows from SMEM, accumulate hs (16 fp32 chains) ----
    float accf[16];
#pragma unroll
    for (int k = 0; k < 16; k++) accf[k] = 0.0f;
#pragma unroll
    for (int t = 0; t < 2; t++) {
        int r = warp * 2 + t;
        float iv = shinv[r];
        const float4* trow = (const float4*)(tile + r * DD);
        float4 y0 = trow[lane];
        float4 y1 = trow[lane + 32];
        float4 y2 = trow[lane + 64];
        float4 y3 = trow[lane + 96];
        accf[0]  = fmaf(y0.x, iv, accf[0]);  accf[1]  = fmaf(y0.y, iv, accf[1]);
        accf[2]  = fmaf(y0.z, iv, accf[2]);  accf[3]  = fmaf(y0.w, iv, accf[3]);
        accf[4]  = fmaf(y1.x, iv, accf[4]);  accf[5]  = fmaf(y1.y, iv, accf[5]);
        accf[6]  = fmaf(y1.z, iv, accf[6]);  accf[7]  = fmaf(y1.w, iv, accf[7]);
        accf[8]  = fmaf(y2.x, iv, accf[8]);  accf[9]  = fmaf(y2.y, iv, accf[9]);
        accf[10] = fmaf(y2.z, iv, accf[10]); accf[11] = fmaf(y2.w, iv, accf[11]);
        accf[12] = fmaf(y3.x, iv, accf[12]); accf[13] = fmaf(y3.y, iv, accf[13]);
        accf[14] = fmaf(y3.z, iv, accf[14]); accf[15] = fmaf(y3.w, iv, accf[15]);
    }
    __syncthreads();   // tile reads done everywhere; reuse tile[0..8*512) as combine buffer
    float* my = tile + warp * DD;
#pragma unroll
    for (int k = 0; k < 4; k++) {
        int c = 4 * (lane + 32 * k);
        my[c + 0] = accf[4 * k + 0];
        my[c + 1] = accf[4 * k + 1];
        my[c + 2] = accf[4 * k + 2];
        my[c + 3] = accf[4 * k + 3];
    }
    __syncthreads();
    for (int c = threadIdx.x; c < DD; c += blockDim.x) {
        double s = 0.0;
#pragma unroll
        for (int w = 0; w < 8; w++) s += (double)tile[w * DD + c];
        atomicAdd(&g_hs[batch * DD + c], s);
    }
}

// ---------------- kernel 3a: t = Wk @ hs (df64, smem-partial) -----------------
// grid = 256 blocks: (batch, 32-row chunk), 256 thr (8 warps), 4 rows/warp.
__global__ void __launch_bounds__(256, 4) matvec1_kernel(const float* __restrict__ Wk) {
    __shared__ float sh_hi[DD];
    __shared__ float sh_lo[DD];
    __shared__ double partd[32 * PAD];
    int b = blockIdx.x >> 4;
    int r0 = (blockIdx.x & 15) * 32;
    for (int i = threadIdx.x; i < DD; i += blockDim.x) {
        double h = g_hs[b * DD + i];
        float hi = (float)h;
        sh_hi[i] = hi;
        sh_lo[i] = (float)(h - (double)hi);
    }
    __syncthreads();

    int warp = threadIdx.x >> 5, lane = threadIdx.x & 31;
#pragma unroll
    for (int t = 0; t < 4; t++) {
        int r = warp * 4 + t;
        const float4* wr = (const float4*)(Wk + (size_t)(r0 + r) * DD);
        float4 x0 = wr[lane];
        float4 x1 = wr[lane + 32];
        float4 x2 = wr[lane + 64];
        float4 x3 = wr[lane + 96];
        float s0 = 0.f, s1 = 0.f, s2 = 0.f, s3 = 0.f;
        float c0 = 0.f, c1 = 0.f, c2 = 0.f, c3 = 0.f;
        int ca = 4 * lane, cb = 4 * (lane + 32), cc = 4 * (lane + 64), cd = 4 * (lane + 96);
        df_acc(x0.x, sh_hi[ca + 0], sh_lo[ca + 0], s0, c0);
        df_acc(x0.y, sh_hi[ca + 1], sh_lo[ca + 1], s1, c1);
        df_acc(x0.z, sh_hi[ca + 2], sh_lo[ca + 2], s2, c2);
        df_acc(x0.w, sh_hi[ca + 3], sh_lo[ca + 3], s3, c3);
        df_acc(x1.x, sh_hi[cb + 0], sh_lo[cb + 0], s0, c0);
        df_acc(x1.y, sh_hi[cb + 1], sh_lo[cb + 1], s1, c1);
        df_acc(x1.z, sh_hi[cb + 2], sh_lo[cb + 2], s2, c2);
        df_acc(x1.w, sh_hi[cb + 3], sh_lo[cb + 3], s3, c3);
        df_acc(x2.x, sh_hi[cc + 0], sh_lo[cc + 0], s0, c0);
        df_acc(x2.y, sh_hi[cc + 1], sh_lo[cc + 1], s1, c1);
        df_acc(x2.z, sh_hi[cc + 2], sh_lo[cc + 2], s2, c2);
        df_acc(x2.w, sh_hi[cc + 3], sh_lo[cc + 3], s3, c3);
        df_acc(x3.x, sh_hi[cd + 0], sh_lo[cd + 0], s0, c0);
        df_acc(x3.y, sh_hi[cd + 1], sh_lo[cd + 1], s1, c1);
        df_acc(x3.z, sh_hi[cd + 2], sh_lo[cd + 2], s2, c2);
        df_acc(x3.w, sh_hi[cd + 3], sh_lo[cd + 3], s3, c3);
        partd[r * PAD + lane] = (((double)s0 + (double)c0) + ((double)s1 + (double)c1))
                              + (((double)s2 + (double)c2) + ((double)s3 + (double)c3));
    }
    __syncwarp();
    if (lane < 4) {
        int r = warp * 4 + lane;
        const double* p = &partd[r * PAD];
        double q[16];
#pragma unroll
        for (int j = 0; j < 16; j++) q[j] = p[j] + p[j + 16];
#pragma unroll
        for (int w = 8; w > 0; w >>= 1)
#pragma unroll
            for (int j = 0; j < 16; j++) if (j < w) q[j] = q[j] + q[j + w];
        g_t[b * DD + r0 + r] = q[0];
    }
}

// ---------------- kernel 3b: vpart (df64, fp32 pipes) --------------------------
__global__ void __launch_bounds__(512, 2) matvec2_kernel(const float* __restrict__ Wq) {
    __shared__ float sh_hi[64];
    __shared__ float sh_lo[64];
    int b = blockIdx.x >> 3;
    int chunk = blockIdx.x & 7;
    int d0 = chunk * 64;
    if (threadIdx.x < 64) {
        double h = g_t[b * DD + d0 + threadIdx.x];
        float hi = (float)h;
        sh_hi[threadIdx.x] = hi;
        sh_lo[threadIdx.x] = (float)(h - (double)hi);
    }
    __syncthreads();

    int e = threadIdx.x;
    const float* wp = Wq + (size_t)d0 * DD + e;
    float s0 = 0.f, s1 = 0.f, s2 = 0.f, s3 = 0.f;
    float c0 = 0.f, c1 = 0.f, c2 = 0.f, c3 = 0.f;
#pragma unroll 4
    for (int d = 0; d < 64; d += 4) {
        float w0 = wp[(size_t)(d + 0) * DD];
        float w1 = wp[(size_t)(d + 1) * DD];
        float w2 = wp[(size_t)(d + 2) * DD];
        float w3 = wp[(size_t)(d + 3) * DD];
        df_acc(w0, sh_hi[d + 0], sh_lo[d + 0], s0, c0);
        df_acc(w1, sh_hi[d + 1], sh_lo[d + 1], s1, c1);
        df_acc(w2, sh_hi[d + 2], sh_lo[d + 2], s2, c2);
        df_acc(w3, sh_hi[d + 3], sh_lo[d + 3], s3, c3);
    }
    double r = (((double)s0 + (double)c0) + ((double)s1 + (double)c1))
             + (((double)s2 + (double)c2) + ((double)s3 + (double)c3));
    g_vpart[((size_t)b * 8 + chunk) * DD + e] = r;
}

// ---------------- kernel 4: scores + hard bits (vpart combine in prologue) ----
__global__ void __launch_bounds__(256, 4) scores_kernel(const float* __restrict__ hidden,
                                                        const float* __restrict__ noise) {
    __shared__ float part[128 * PAD];
    __shared__ float sh_v[DD];
    int warp = threadIdx.x >> 5;
    int lane = threadIdx.x & 31;
    int batch = blockIdx.x >> 6;
    int tok0  = ((blockIdx.x & 63) * 8 + warp) * 16;

    // combine vpart chunks (fixed order; vpart is 512KB, L2-resident)
    for (int i = threadIdx.x; i < DD; i += blockDim.x) {
        double s = 0.0;
#pragma unroll
        for (int c = 0; c < 8; c++) s += g_vpart[((size_t)batch * 8 + c) * DD + i];
        sh_v[i] = (float)s;
    }
    __syncthreads();

    const float4* vv = (const float4*)sh_v;
    float4 w0 = vv[lane], w1 = vv[lane + 32], w2 = vv[lane + 64], w3 = vv[lane + 96];

    const float4* base = (const float4*)(hidden + (size_t)batch * SS * DD);
#pragma unroll
    for (int t = 0; t < 16; t += 2) {
#pragma unroll
        for (int i = 0; i < 2; i++) {
            const float4* row = base + (size_t)(tok0 + t + i) * (DD / 4);
            float4 x0 = row[lane];
            float4 x1 = row[lane + 32];
            float4 x2 = row[lane + 64];
            float4 x3 = row[lane + 96];
            float s0 = 0.f, s1 = 0.f, s2 = 0.f, s3 = 0.f;
            s0 = fmaf(x0.x, w0.x, s0); s1 = fmaf(x0.y, w0.y, s1);
            s2 = fmaf(x0.z, w0.z, s2); s3 = fmaf(x0.w, w0.w, s3);
            s0 = fmaf(x1.x, w1.x, s0); s1 = fmaf(x1.y, w1.y, s1);
            s2 = fmaf(x1.z, w1.z, s2); s3 = fmaf(x1.w, w1.w, s3);
            s0 = fmaf(x2.x, w2.x, s0); s1 = fmaf(x2.y, w2.y, s1);
            s2 = fmaf(x2.z, w2.z, s2); s3 = fmaf(x2.w, w2.w, s3);
            s0 = fmaf(x3.x, w3.x, s0); s1 = fmaf(x3.y, w3.y, s1);
            s2 = fmaf(x3.z, w3.z, s2); s3 = fmaf(x3.w, w3.w, s3);
            part[(warp * 16 + t + i) * PAD + lane] = (s0 + s1) + (s2 + s3);
        }
    }
    __syncwarp();
    if (lane < 16) {
        int r = warp * 16 + lane;
        const float* p = &part[r * PAD];
        double q[16];
#pragma unroll
        for (int j = 0; j < 16; j++) q[j] = (double)p[j] + (double)p[j + 16];
#pragma unroll
        for (int w = 8; w > 0; w >>= 1)
#pragma unroll
            for (int j = 0; j < 16; j++) if (j < w) q[j] = q[j] + q[j + w];
        int g = batch * SS + tok0 + lane;
        double score = SCALE_F * (double)g_invnorm[g] * q[0];
        float nz = noise[g];
        double logistic = (double)logf(nz) - (double)log1pf(-nz);
        g_hard[g] = (score + logistic > 0.0) ? 1 : 0;
    }
}

// ---------------- kernel 5: per-batch stable compaction scan ------------------
__global__ void scan_kernel() {
    int b = blockIdx.x;
    int tid = threadIdx.x;
    const int TPT = SS / 1024;  // 8
    int base = b * SS + tid * TPT;

    int loc[TPT];
    int cnt = 0;
#pragma unroll
    for (int i = 0; i < TPT; i++) { loc[i] = g_hard[base + i]; cnt += loc[i]; }

    int lane = tid & 31, warp = tid >> 5;
    int v = cnt;
#pragma unroll
    for (int o = 1; o < 32; o <<= 1) {
        int n = __shfl_up_sync(0xffffffffu, v, o);
        if (lane >= o) v += n;
    }
    __shared__ int wsum[32];
    if (lane == 31) wsum[warp] = v;
    __syncthreads();
    if (warp == 0) {
        int w = wsum[lane];
#pragma unroll
        for (int o = 1; o < 32; o <<= 1) {
            int n = __shfl_up_sync(0xffffffffu, w, o);
            if (lane >= o) w += n;
        }
        wsum[lane] = w;
    }
    __syncthreads();
    int excl = (v - cnt) + (warp > 0 ? wsum[warp - 1] : 0);

    int pos = excl;
#pragma unroll
    for (int i = 0; i < TPT; i++)
        if (loc[i]) g_keptidx[b * SS + (pos++)] = tid * TPT + i;
    if (tid == 1023) g_count[b] = excl + cnt;
}

// ---------------- kernel 6: write pooled (gather kept rows, zero the rest) ----
__global__ void __launch_bounds__(256, 4) writeout_kernel(const float* __restrict__ hidden,
                                                          float* __restrict__ out) {
    int wg = blockIdx.x * (blockDim.x >> 5) + (threadIdx.x >> 5);
    int lane = threadIdx.x & 31;
    int b = wg >> 12;          // 4096 warps per batch (2 rows each)
    int i0 = (wg & 4095) * 2;
    int cnt = g_count[b];

    bool v0 = i0 < cnt, v1 = (i0 + 1) < cnt;
    int s0 = v0 ? g_keptidx[b * SS + i0] : 0;
    int s1 = v1 ? g_keptidx[b * SS + i0 + 1] : 0;
    float inv0 = v0 ? g_invnorm[b * SS + s0] : 0.f;
    float inv1 = v1 ? g_invnorm[b * SS + s1] : 0.f;

    const float4* r0 = (const float4*)hidden + ((size_t)b * SS + s0) * (DD / 4);
    const float4* r1 = (const float4*)hidden + ((size_t)b * SS + s1) * (DD / 4);
    float4 a[4], c[4];
    float4 z = make_float4(0.f, 0.f, 0.f, 0.f);
#pragma unroll
    for (int k = 0; k < 4; k++) a[k] = v0 ? r0[lane + 32 * k] : z;
#pragma unroll
    for (int k = 0; k < 4; k++) c[k] = v1 ? r1[lane + 32 * k] : z;

    float4* o0 = (float4*)out + ((size_t)b * SS + i0) * (DD / 4);
    float4* o1 = o0 + (DD / 4);
#pragma unroll
    for (int k = 0; k < 4; k++) {
        float4 x = a[k];
        x.x *= inv0; x.y *= inv0; x.z *= inv0; x.w *= inv0;
        o0[lane + 32 * k] = x;
    }
#pragma unroll
    for (int k = 0; k < 4; k++) {
        float4 x = c[k];
        x.x *= inv1; x.y *= inv1; x.z *= inv1; x.w *= inv1;
        o1[lane + 32 * k] = x;
    }
}

// ---------------- kernel 7: binomial loss -> tail of output -------------------
__global__ void loss_kernel(float* __restrict__ out, long long out_size) {
    __shared__ double sh[BB];
    __shared__ float sh_loss;
    int tid = threadIdx.x;
    if (tid < BB) {
        double k = (double)g_count[tid];
        double n = (double)SS;
        double lp = lgamma(n + 1.0) - lgamma(k + 1.0) - lgamma(n - k + 1.0)
                  + k * log(0.2) + (n - k) * log1p(-0.2);
        sh[tid] = lp;
    }
    __syncthreads();
    if (tid == 0) {
        double m = 0.0;
        for (int b = 0; b < BB; b++) m += sh[b];
        m /= (double)BB;
        sh_loss = (float)(-m / (double)SS);
    }
    __syncthreads();
    long long start = (long long)BB * SS * DD;
    for (long long i = start + tid; i < out_size; i += blockDim.x) out[i] = sh_loss;
}

// ---------------- launch ------------------------------------------------------
extern "C" void kernel_launch(void* const* d_in, const int* in_sizes, int n_in,
                              void* d_out, int out_size) {
    const float* hidden = (const float*)d_in[0];
    const float* Wq     = (const float*)d_in[1];
    const float* Wk     = (const float*)d_in[2];
    const float* noise  = (const float*)d_in[3];
    float* out = (float*)d_out;

    // dyn smem for normhs: tile(16*512) + part(16*33) + shinv(16) floats ≈ 34.8KB
    const int NORMHS_SMEM = (16 * DD + 16 * PAD + 16) * (int)sizeof(float);

    zero_hs_kernel<<<(BB * DD + 511) / 512, 512>>>();
    normhs_kernel<<<BB * 512, 256, NORMHS_SMEM>>>(hidden);
    matvec1_kernel<<<BB * 16, 256>>>(Wk);
    matvec2_kernel<<<BB * 8, 512>>>(Wq);
    scores_kernel<<<1024, 256>>>(hidden, noise);
    scan_kernel<<<BB, 1024>>>();
    writeout_kernel<<<(BB * SS) / 16, 256>>>(hidden, out);
    loss_kernel<<<1, 256>>>(out, (long long)out_size);
}

// round 13
// speedup vs baseline: 1.1869x; 1.1869x over previous
#include <cuda_runtime.h>
#include <math.h>

#define BB 16
#define SS 8192
#define DD 512
#define SCALE_F 0.125
#define PAD 33   // smem row pad: conflict-free scalar reads

// ---------------- scratch (__device__ globals; no allocations allowed) --------
__device__ double        g_hs[BB * DD];        // sum of normalized tokens (fp64)
__device__ double        g_t[BB * DD];         // t = Wk @ hs (fp64)
__device__ double        g_vpart[BB * 8 * DD]; // stage2 partials (fp64)
__device__ float         g_v[BB * DD];         // v[b] = Wq^T (Wk hs[b])
__device__ float         g_invnorm[BB * SS];   // 1/max(||hidden_row||, 1e-12)
__device__ unsigned char g_hard[BB * SS];      // boundary bits
__device__ int           g_keptidx[BB * SS];   // compacted kept indices per batch
__device__ int           g_count[BB];          // kept counts

// ---- df64 helpers: exact product + Knuth two-sum compensated accumulation ----
__device__ __forceinline__ void df_acc(float x, float hi, float lo,
                                       float& s, float& c) {
    float p_hi = x * hi;
    float p_lo = fmaf(x, hi, -p_hi);
    p_lo = fmaf(x, lo, p_lo);
    float t  = s + p_hi;
    float bv = t - s;
    float e  = (s - (t - bv)) + (p_hi - bv);
    s = t;
    c += e + p_lo;
}

// ---------------- kernel 0: zero hs ------------------------------------------
__global__ void zero_hs_kernel() {
    int i = blockIdx.x * blockDim.x + threadIdx.x;
    if (i < BB * DD) g_hs[i] = 0.0;
}

// ---------------- kernel 1: fused invnorm + hs, SINGLE pass over hidden -------
// grid = 4096 (256 per batch), 256 thr (8 warps), 32 tokens/block (4/warp).
// smem = tile(32*512) + part(32*33) + shinv(32) ≈ 68.3KB -> 3 blocks/SM.
// Phase A: stream rows global->SMEM tile + fp32 sumsq partials
// Phase B: lanes 0-3 tree-reduce one token each -> invnorm
// Phase C: re-read rows from SMEM, accumulate hs; tile reused as combine buffer.
__global__ void __launch_bounds__(256, 2) normhs_kernel(const float* __restrict__ hidden) {
    extern __shared__ float dyn[];
    float* tile  = dyn;                       // 32 * 512 (reused as wacc later)
    float* part  = dyn + 32 * DD;             // 32 * PAD
    float* shinv = part + 32 * PAD;           // 32

    int warp = threadIdx.x >> 5;
    int lane = threadIdx.x & 31;
    int batch = blockIdx.x >> 8;                     // 256 blocks per batch
    int tokb  = (blockIdx.x & 255) * 32;             // block token base
    int tok0  = tokb + warp * 4;                     // warp token base

    const float4* base = (const float4*)(hidden + (size_t)batch * SS * DD);

    // ---- phase A: global -> sumsq partials + SMEM tile (pure stream) ----
#pragma unroll
    for (int t = 0; t < 4; t++) {
        int r = warp * 4 + t;
        const float4* row = base + (size_t)(tok0 + t) * (DD / 4);
        float4* trow = (float4*)(tile + r * DD);
        float4 x0 = row[lane];
        float4 x1 = row[lane + 32];
        float4 x2 = row[lane + 64];
        float4 x3 = row[lane + 96];
        float s0 = 0.f, s1 = 0.f, s2 = 0.f, s3 = 0.f;
        s0 = fmaf(x0.x, x0.x, s0); s1 = fmaf(x0.y, x0.y, s1);
        s2 = fmaf(x0.z, x0.z, s2); s3 = fmaf(x0.w, x0.w, s3);
        s0 = fmaf(x1.x, x1.x, s0); s1 = fmaf(x1.y, x1.y, s1);
        s2 = fmaf(x1.z, x1.z, s2); s3 = fmaf(x1.w, x1.w, s3);
        s0 = fmaf(x2.x, x2.x, s0); s1 = fmaf(x2.y, x2.y, s1);
        s2 = fmaf(x2.z, x2.z, s2); s3 = fmaf(x2.w, x2.w, s3);
        s0 = fmaf(x3.x, x3.x, s0); s1 = fmaf(x3.y, x3.y, s1);
        s2 = fmaf(x3.z, x3.z, s2); s3 = fmaf(x3.w, x3.w, s3);
        trow[lane]      = x0;
        trow[lane + 32] = x1;
        trow[lane + 64] = x2;
        trow[lane + 96] = x3;
        part[r * PAD + lane] = (s0 + s1) + (s2 + s3);
    }
    __syncwarp();

    // ---- phase B: lanes 0-3 reduce one token each (fp32 pairwise tree) ----
    if (lane < 4) {
        int r = warp * 4 + lane;
        const float* p = &part[r * PAD];
        float q[32];
#pragma unroll
        for (int j = 0; j < 32; j++) q[j] = p[j];
#pragma unroll
        for (int w = 16; w > 0; w >>= 1)
#pragma unroll
            for (int j = 0; j < 32; j++) if (j < w) q[j] = q[j] + q[j + w];
        float iv = 1.0f / fmaxf(sqrtf(q[0]), 1e-12f);
        g_invnorm[batch * SS + tok0 + lane] = iv;
        shinv[r] = iv;
    }
    __syncwarp();

    // ---- phase C: re-read rows from SMEM, accumulate hs (16 fp32 chains) ----
    float accf[16];
#pragma unroll
    for (int k = 0; k < 16; k++) accf[k] = 0.0f;
#pragma unroll
    for (int t = 0; t < 4; t++) {
        int r = warp * 4 + t;
        float iv = shinv[r];
        const float4* trow = (const float4*)(tile + r * DD);
        float4 y0 = trow[lane];
        float4 y1 = trow[lane + 32];
        float4 y2 = trow[lane + 64];
        float4 y3 = trow[lane + 96];
        accf[0]  = fmaf(y0.x, iv, accf[0]);  accf[1]  = fmaf(y0.y, iv, accf[1]);
        accf[2]  = fmaf(y0.z, iv, accf[2]);  accf[3]  = fmaf(y0.w, iv, accf[3]);
        accf[4]  = fmaf(y1.x, iv, accf[4]);  accf[5]  = fmaf(y1.y, iv, accf[5]);
        accf[6]  = fmaf(y1.z, iv, accf[6]);  accf[7]  = fmaf(y1.w, iv, accf[7]);
        accf[8]  = fmaf(y2.x, iv, accf[8]);  accf[9]  = fmaf(y2.y, iv, accf[9]);
        accf[10] = fmaf(y2.z, iv, accf[10]); accf[11] = fmaf(y2.w, iv, accf[11]);
        accf[12] = fmaf(y3.x, iv, accf[12]); accf[13] = fmaf(y3.y, iv, accf[13]);
        accf[14] = fmaf(y3.z, iv, accf[14]); accf[15] = fmaf(y3.w, iv, accf[15]);
    }
    __syncthreads();   // all tile reads done; reuse tile[0..8*512) as combine buffer
    float* my = tile + warp * DD;
#pragma unroll
    for (int k = 0; k < 4; k++) {
        int c = 4 * (lane + 32 * k);
        my[c + 0] = accf[4 * k + 0];
        my[c + 1] = accf[4 * k + 1];
        my[c + 2] = accf[4 * k + 2];
        my[c + 3] = accf[4 * k + 3];
    }
    __syncthreads();
    for (int c = threadIdx.x; c < DD; c += blockDim.x) {
        double s = 0.0;
#pragma unroll
        for (int w = 0; w < 8; w++) s += (double)tile[w * DD + c];
        atomicAdd(&g_hs[batch * DD + c], s);
    }
}

// ---------------- kernel 3a: t = Wk @ hs (df64, smem-partial) -----------------
// grid = 256 blocks: (batch, 32-row chunk), 256 thr (8 warps), 4 rows/warp.
__global__ void __launch_bounds__(256, 4) matvec1_kernel(const float* __restrict__ Wk) {
    __shared__ float sh_hi[DD];
    __shared__ float sh_lo[DD];
    __shared__ double partd[32 * PAD];
    int b = blockIdx.x >> 4;
    int r0 = (blockIdx.x & 15) * 32;
    for (int i = threadIdx.x; i < DD; i += blockDim.x) {
        double h = g_hs[b * DD + i];
        float hi = (float)h;
        sh_hi[i] = hi;
        sh_lo[i] = (float)(h - (double)hi);
    }
    __syncthreads();

    int warp = threadIdx.x >> 5, lane = threadIdx.x & 31;
#pragma unroll
    for (int t = 0; t < 4; t++) {
        int r = warp * 4 + t;
        const float4* wr = (const float4*)(Wk + (size_t)(r0 + r) * DD);
        float4 x0 = wr[lane];
        float4 x1 = wr[lane + 32];
        float4 x2 = wr[lane + 64];
        float4 x3 = wr[lane + 96];
        float s0 = 0.f, s1 = 0.f, s2 = 0.f, s3 = 0.f;
        float c0 = 0.f, c1 = 0.f, c2 = 0.f, c3 = 0.f;
        int ca = 4 * lane, cb = 4 * (lane + 32), cc = 4 * (lane + 64), cd = 4 * (lane + 96);
        df_acc(x0.x, sh_hi[ca + 0], sh_lo[ca + 0], s0, c0);
        df_acc(x0.y, sh_hi[ca + 1], sh_lo[ca + 1], s1, c1);
        df_acc(x0.z, sh_hi[ca + 2], sh_lo[ca + 2], s2, c2);
        df_acc(x0.w, sh_hi[ca + 3], sh_lo[ca + 3], s3, c3);
        df_acc(x1.x, sh_hi[cb + 0], sh_lo[cb + 0], s0, c0);
        df_acc(x1.y, sh_hi[cb + 1], sh_lo[cb + 1], s1, c1);
        df_acc(x1.z, sh_hi[cb + 2], sh_lo[cb + 2], s2, c2);
        df_acc(x1.w, sh_hi[cb + 3], sh_lo[cb + 3], s3, c3);
        df_acc(x2.x, sh_hi[cc + 0], sh_lo[cc + 0], s0, c0);
        df_acc(x2.y, sh_hi[cc + 1], sh_lo[cc + 1], s1, c1);
        df_acc(x2.z, sh_hi[cc + 2], sh_lo[cc + 2], s2, c2);
        df_acc(x2.w, sh_hi[cc + 3], sh_lo[cc + 3], s3, c3);
        df_acc(x3.x, sh_hi[cd + 0], sh_lo[cd + 0], s0, c0);
        df_acc(x3.y, sh_hi[cd + 1], sh_lo[cd + 1], s1, c1);
        df_acc(x3.z, sh_hi[cd + 2], sh_lo[cd + 2], s2, c2);
        df_acc(x3.w, sh_hi[cd + 3], sh_lo[cd + 3], s3, c3);
        partd[r * PAD + lane] = (((double)s0 + (double)c0) + ((double)s1 + (double)c1))
                              + (((double)s2 + (double)c2) + ((double)s3 + (double)c3));
    }
    __syncwarp();
    if (lane < 4) {
        int r = warp * 4 + lane;
        const double* p = &partd[r * PAD];
        double q[16];
#pragma unroll
        for (int j = 0; j < 16; j++) q[j] = p[j] + p[j + 16];
#pragma unroll
        for (int w = 8; w > 0; w >>= 1)
#pragma unroll
            for (int j = 0; j < 16; j++) if (j < w) q[j] = q[j] + q[j + w];
        g_t[b * DD + r0 + r] = q[0];
    }
}

// ---------------- kernel 3b: vpart (df64, fp32 pipes) --------------------------
__global__ void __launch_bounds__(512, 2) matvec2_kernel(const float* __restrict__ Wq) {
    __shared__ float sh_hi[64];
    __shared__ float sh_lo[64];
    int b = blockIdx.x >> 3;
    int chunk = blockIdx.x & 7;
    int d0 = chunk * 64;
    if (threadIdx.x < 64) {
        double h = g_t[b * DD + d0 + threadIdx.x];
        float hi = (float)h;
        sh_hi[threadIdx.x] = hi;
        sh_lo[threadIdx.x] = (float)(h - (double)hi);
    }
    __syncthreads();

    int e = threadIdx.x;
    const float* wp = Wq + (size_t)d0 * DD + e;
    float s0 = 0.f, s1 = 0.f, s2 = 0.f, s3 = 0.f;
    float c0 = 0.f, c1 = 0.f, c2 = 0.f, c3 = 0.f;
#pragma unroll 4
    for (int d = 0; d < 64; d += 4) {
        float w0 = wp[(size_t)(d + 0) * DD];
        float w1 = wp[(size_t)(d + 1) * DD];
        float w2 = wp[(size_t)(d + 2) * DD];
        float w3 = wp[(size_t)(d + 3) * DD];
        df_acc(w0, sh_hi[d + 0], sh_lo[d + 0], s0, c0);
        df_acc(w1, sh_hi[d + 1], sh_lo[d + 1], s1, c1);
        df_acc(w2, sh_hi[d + 2], sh_lo[d + 2], s2, c2);
        df_acc(w3, sh_hi[d + 3], sh_lo[d + 3], s3, c3);
    }
    double r = (((double)s0 + (double)c0) + ((double)s1 + (double)c1))
             + (((double)s2 + (double)c2) + ((double)s3 + (double)c3));
    g_vpart[((size_t)b * 8 + chunk) * DD + e] = r;
}

// ---------------- kernel 3c: combine partials -> g_v (fixed order) ------------
__global__ void matvec3_kernel() {
    int b = blockIdx.x;
    int e = threadIdx.x;
    double s = 0.0;
#pragma unroll
    for (int c = 0; c < 8; c++) s += g_vpart[((size_t)b * 8 + c) * DD + e];
    g_v[b * DD + e] = (float)s;
}

// ---------------- kernel 4: scores + hard bits (stream + warp-local reduce) ---
__global__ void __launch_bounds__(256, 4) scores_kernel(const float* __restrict__ hidden,
                                                        const float* __restrict__ noise) {
    __shared__ float part[128 * PAD];
    __shared__ float sh_v[DD];
    int warp = threadIdx.x >> 5;
    int lane = threadIdx.x & 31;
    int batch = blockIdx.x >> 6;
    int tok0  = ((blockIdx.x & 63) * 8 + warp) * 16;

    for (int i = threadIdx.x; i < DD; i += blockDim.x) sh_v[i] = g_v[batch * DD + i];
    __syncthreads();

    const float4* vv = (const float4*)sh_v;
    float4 w0 = vv[lane], w1 = vv[lane + 32], w2 = vv[lane + 64], w3 = vv[lane + 96];

    const float4* base = (const float4*)(hidden + (size_t)batch * SS * DD);
#pragma unroll
    for (int t = 0; t < 16; t += 2) {
#pragma unroll
        for (int i = 0; i < 2; i++) {
            const float4* row = base + (size_t)(tok0 + t + i) * (DD / 4);
            float4 x0 = row[lane];
            float4 x1 = row[lane + 32];
            float4 x2 = row[lane + 64];
            float4 x3 = row[lane + 96];
            float s0 = 0.f, s1 = 0.f, s2 = 0.f, s3 = 0.f;
            s0 = fmaf(x0.x, w0.x, s0); s1 = fmaf(x0.y, w0.y, s1);
            s2 = fmaf(x0.z, w0.z, s2); s3 = fmaf(x0.w, w0.w, s3);
            s0 = fmaf(x1.x, w1.x, s0); s1 = fmaf(x1.y, w1.y, s1);
            s2 = fmaf(x1.z, w1.z, s2); s3 = fmaf(x1.w, w1.w, s3);
            s0 = fmaf(x2.x, w2.x, s0); s1 = fmaf(x2.y, w2.y, s1);
            s2 = fmaf(x2.z, w2.z, s2); s3 = fmaf(x2.w, w2.w, s3);
            s0 = fmaf(x3.x, w3.x, s0); s1 = fmaf(x3.y, w3.y, s1);
            s2 = fmaf(x3.z, w3.z, s2); s3 = fmaf(x3.w, w3.w, s3);
            part[(warp * 16 + t + i) * PAD + lane] = (s0 + s1) + (s2 + s3);
        }
    }
    __syncwarp();
    if (lane < 16) {
        int r = warp * 16 + lane;
        const float* p = &part[r * PAD];
        double q[16];
#pragma unroll
        for (int j = 0; j < 16; j++) q[j] = (double)p[j] + (double)p[j + 16];
#pragma unroll
        for (int w = 8; w > 0; w >>= 1)
#pragma unroll
            for (int j = 0; j < 16; j++) if (j < w) q[j] = q[j] + q[j + w];
        int g = batch * SS + tok0 + lane;
        double score = SCALE_F * (double)g_invnorm[g] * q[0];
        float nz = noise[g];
        double logistic = (double)logf(nz) - (double)log1pf(-nz);
        g_hard[g] = (score + logistic > 0.0) ? 1 : 0;
    }
}

// ---------------- kernel 5: per-batch stable compaction scan ------------------
__global__ void scan_kernel() {
    int b = blockIdx.x;
    int tid = threadIdx.x;
    const int TPT = SS / 1024;  // 8
    int base = b * SS + tid * TPT;

    int loc[TPT];
    int cnt = 0;
#pragma unroll
    for (int i = 0; i < TPT; i++) { loc[i] = g_hard[base + i]; cnt += loc[i]; }

    int lane = tid & 31, warp = tid >> 5;
    int v = cnt;
#pragma unroll
    for (int o = 1; o < 32; o <<= 1) {
        int n = __shfl_up_sync(0xffffffffu, v, o);
        if (lane >= o) v += n;
    }
    __shared__ int wsum[32];
    if (lane == 31) wsum[warp] = v;
    __syncthreads();
    if (warp == 0) {
        int w = wsum[lane];
#pragma unroll
        for (int o = 1; o < 32; o <<= 1) {
            int n = __shfl_up_sync(0xffffffffu, w, o);
            if (lane >= o) w += n;
        }
        wsum[lane] = w;
    }
    __syncthreads();
    int excl = (v - cnt) + (warp > 0 ? wsum[warp - 1] : 0);

    int pos = excl;
#pragma unroll
    for (int i = 0; i < TPT; i++)
        if (loc[i]) g_keptidx[b * SS + (pos++)] = tid * TPT + i;
    if (tid == 1023) g_count[b] = excl + cnt;
}

// ---------------- kernel 6: write pooled (gather kept rows, zero the rest) ----
__global__ void __launch_bounds__(256, 4) writeout_kernel(const float* __restrict__ hidden,
                                                          float* __restrict__ out) {
    int wg = blockIdx.x * (blockDim.x >> 5) + (threadIdx.x >> 5);
    int lane = threadIdx.x & 31;
    int b = wg >> 12;          // 4096 warps per batch (2 rows each)
    int i0 = (wg & 4095) * 2;
    int cnt = g_count[b];

    bool v0 = i0 < cnt, v1 = (i0 + 1) < cnt;
    int s0 = v0 ? g_keptidx[b * SS + i0] : 0;
    int s1 = v1 ? g_keptidx[b * SS + i0 + 1] : 0;
    float inv0 = v0 ? g_invnorm[b * SS + s0] : 0.f;
    float inv1 = v1 ? g_invnorm[b * SS + s1] : 0.f;

    const float4* r0 = (const float4*)hidden + ((size_t)b * SS + s0) * (DD / 4);
    const float4* r1 = (const float4*)hidden + ((size_t)b * SS + s1) * (DD / 4);
    float4 a[4], c[4];
    float4 z = make_float4(0.f, 0.f, 0.f, 0.f);
#pragma unroll
    for (int k = 0; k < 4; k++) a[k] = v0 ? r0[lane + 32 * k] : z;
#pragma unroll
    for (int k = 0; k < 4; k++) c[k] = v1 ? r1[lane + 32 * k] : z;

    float4* o0 = (float4*)out + ((size_t)b * SS + i0) * (DD / 4);
    float4* o1 = o0 + (DD / 4);
#pragma unroll
    for (int k = 0; k < 4; k++) {
        float4 x = a[k];
        x.x *= inv0; x.y *= inv0; x.z *= inv0; x.w *= inv0;
        o0[lane + 32 * k] = x;
    }
#pragma unroll
    for (int k = 0; k < 4; k++) {
        float4 x = c[k];
        x.x *= inv1; x.y *= inv1; x.z *= inv1; x.w *= inv1;
        o1[lane + 32 * k] = x;
    }
}

// ---------------- kernel 7: binomial loss -> tail of output -------------------
__global__ void loss_kernel(float* __restrict__ out, long long out_size) {
    __shared__ double sh[BB];
    __shared__ float sh_loss;
    int tid = threadIdx.x;
    if (tid < BB) {
        double k = (double)g_count[tid];
        double n = (double)SS;
        double lp = lgamma(n + 1.0) - lgamma(k + 1.0) - lgamma(n - k + 1.0)
                  + k * log(0.2) + (n - k) * log1p(-0.2);
        sh[tid] = lp;
    }
    __syncthreads();
    if (tid == 0) {
        double m = 0.0;
        for (int b = 0; b < BB; b++) m += sh[b];
        m /= (double)BB;
        sh_loss = (float)(-m / (double)SS);
    }
    __syncthreads();
    long long start = (long long)BB * SS * DD;
    for (long long i = start + tid; i < out_size; i += blockDim.x) out[i] = sh_loss;
}

// ---------------- launch ------------------------------------------------------
extern "C" void kernel_launch(void* const* d_in, const int* in_sizes, int n_in,
                              void* d_out, int out_size) {
    const float* hidden = (const float*)d_in[0];
    const float* Wq     = (const float*)d_in[1];
    const float* Wk     = (const float*)d_in[2];
    const float* noise  = (const float*)d_in[3];
    float* out = (float*)d_out;

    // dyn smem for normhs: tile(32*512) + part(32*33) + shinv(32) ≈ 68.3KB
    const int NORMHS_SMEM = (32 * DD + 32 * PAD + 32) * (int)sizeof(float);
    static int s_attr_done = 0;
    if (!s_attr_done) {
        cudaFuncSetAttribute(normhs_kernel,
                             cudaFuncAttributeMaxDynamicSharedMemorySize, NORMHS_SMEM);
        s_attr_done = 1;
    }

    zero_hs_kernel<<<(BB * DD + 511) / 512, 512>>>();
    normhs_kernel<<<4096, 256, NORMHS_SMEM>>>(hidden);
    matvec1_kernel<<<BB * 16, 256>>>(Wk);
    matvec2_kernel<<<BB * 8, 512>>>(Wq);
    matvec3_kernel<<<BB, DD>>>();
    scores_kernel<<<1024, 256>>>(hidden, noise);
    scan_kernel<<<BB, 1024>>>();
    writeout_kernel<<<(BB * SS) / 16, 256>>>(hidden, out);
    loss_kernel<<<1, 256>>>(out, (long long)out_size);
}

// round 14
// speedup vs baseline: 1.2880x; 1.0852x over previous
#include <cuda_runtime.h>
#include <math.h>

#define BB 16
#define SS 8192
#define DD 512
#define SCALE_F 0.125
#define PAD 33   // smem row pad: conflict-free scalar reads

// ---------------- scratch (__device__ globals; no allocations allowed) --------
__device__ double        g_hs[BB * DD];        // sum of normalized tokens (fp64)
__device__ double        g_t[BB * DD];         // t = Wk @ hs (fp64)
__device__ double        g_vpart[BB * 8 * DD]; // stage2 partials (fp64)
__device__ float         g_v[BB * DD];         // v[b] = Wq^T (Wk hs[b])
__device__ float         g_invnorm[BB * SS];   // 1/max(||hidden_row||, 1e-12)
__device__ unsigned char g_hard[BB * SS];      // boundary bits
__device__ int           g_keptidx[BB * SS];   // compacted kept indices per batch
__device__ int           g_count[BB];          // kept counts

// ---- df64 helpers: exact product + Knuth two-sum compensated accumulation ----
__device__ __forceinline__ void df_acc(float x, float hi, float lo,
                                       float& s, float& c) {
    float p_hi = x * hi;
    float p_lo = fmaf(x, hi, -p_hi);
    p_lo = fmaf(x, lo, p_lo);
    float t  = s + p_hi;
    float bv = t - s;
    float e  = (s - (t - bv)) + (p_hi - bv);
    s = t;
    c += e + p_lo;
}

// ---------------- kernel 0: zero hs ------------------------------------------
__global__ void zero_hs_kernel() {
    int i = blockIdx.x * blockDim.x + threadIdx.x;
    if (i < BB * DD) g_hs[i] = 0.0;
}

// ---------------- kernel 1: fused invnorm + hs, register-resident single pass -
// grid = 1024 (64 per batch), 256 thr (8 warps), warp = 16 tokens, 2/iteration.
// Per pair: 8 LDG.128 -> fp32 sumsq (4 chains/row) -> interleaved fp32
// butterflies -> invnorm; same registers then feed 16 fp32 hs chains.
// smem only 16KB (warp-combine buffer); fp64 atomics: 1024*512 = 0.5M.
// Butterfly ordering identical to rounds 3-4 (measured rel_err 3.20067e-06).
__global__ void __launch_bounds__(256, 2) normhs_kernel(const float* __restrict__ hidden) {
    __shared__ float wacc[8 * DD];   // 16 KB
    int warp = threadIdx.x >> 5;
    int lane = threadIdx.x & 31;
    int batch = blockIdx.x >> 6;                       // 64 blocks per batch
    int tok0  = ((blockIdx.x & 63) * 8 + warp) * 16;   // 16 tokens per warp

    float accf[16];
#pragma unroll
    for (int k = 0; k < 16; k++) accf[k] = 0.0f;

    const float4* base = (const float4*)(hidden + (size_t)batch * SS * DD);
#pragma unroll
    for (int t = 0; t < 16; t += 2) {
        // ---- load 2 rows (8 LDG.128 in flight) ----
        float4 x[2][4];
#pragma unroll
        for (int i = 0; i < 2; i++) {
            const float4* row = base + (size_t)(tok0 + t + i) * (DD / 4);
#pragma unroll
            for (int k = 0; k < 4; k++) x[i][k] = row[lane + 32 * k];
        }
        // ---- per-lane sumsq: fp32, 4 independent chains/row ----
        float ss[2];
#pragma unroll
        for (int i = 0; i < 2; i++) {
            float s0 = 0.f, s1 = 0.f, s2 = 0.f, s3 = 0.f;
#pragma unroll
            for (int k = 0; k < 4; k++) {
                s0 = fmaf(x[i][k].x, x[i][k].x, s0);
                s1 = fmaf(x[i][k].y, x[i][k].y, s1);
                s2 = fmaf(x[i][k].z, x[i][k].z, s2);
                s3 = fmaf(x[i][k].w, x[i][k].w, s3);
            }
            ss[i] = (s0 + s1) + (s2 + s3);
        }
        // ---- interleaved fp32 butterflies (2 independent chains) ----
#pragma unroll
        for (int o = 16; o > 0; o >>= 1) {
            ss[0] += __shfl_xor_sync(0xffffffffu, ss[0], o);
            ss[1] += __shfl_xor_sync(0xffffffffu, ss[1], o);
        }
        float inv0 = 1.0f / fmaxf(sqrtf(ss[0]), 1e-12f);
        float inv1 = 1.0f / fmaxf(sqrtf(ss[1]), 1e-12f);
        if (lane < 2)
            g_invnorm[batch * SS + tok0 + t + lane] = (lane == 0) ? inv0 : inv1;
        // ---- hs accumulation: same regs, 16 independent fp32 chains ----
#pragma unroll
        for (int k = 0; k < 4; k++) {
            accf[4 * k + 0] = fmaf(x[0][k].x, inv0, accf[4 * k + 0]);
            accf[4 * k + 1] = fmaf(x[0][k].y, inv0, accf[4 * k + 1]);
            accf[4 * k + 2] = fmaf(x[0][k].z, inv0, accf[4 * k + 2]);
            accf[4 * k + 3] = fmaf(x[0][k].w, inv0, accf[4 * k + 3]);
            accf[4 * k + 0] = fmaf(x[1][k].x, inv1, accf[4 * k + 0]);
            accf[4 * k + 1] = fmaf(x[1][k].y, inv1, accf[4 * k + 1]);
            accf[4 * k + 2] = fmaf(x[1][k].z, inv1, accf[4 * k + 2]);
            accf[4 * k + 3] = fmaf(x[1][k].w, inv1, accf[4 * k + 3]);
        }
    }
    // ---- per-warp partials -> smem, block fp64 combine, one atomic/column ----
    float* my = wacc + warp * DD;
#pragma unroll
    for (int k = 0; k < 4; k++) {
        int c = 4 * (lane + 32 * k);
        my[c + 0] = accf[4 * k + 0];
        my[c + 1] = accf[4 * k + 1];
        my[c + 2] = accf[4 * k + 2];
        my[c + 3] = accf[4 * k + 3];
    }
    __syncthreads();
    for (int c = threadIdx.x; c < DD; c += blockDim.x) {
        double s = 0.0;
#pragma unroll
        for (int w = 0; w < 8; w++) s += (double)wacc[w * DD + c];
        atomicAdd(&g_hs[batch * DD + c], s);
    }
}

// ---------------- kernel 3a: t = Wk @ hs (df64, smem-partial) -----------------
// grid = 256 blocks: (batch, 32-row chunk), 256 thr (8 warps), 4 rows/warp.
__global__ void __launch_bounds__(256, 4) matvec1_kernel(const float* __restrict__ Wk) {
    __shared__ float sh_hi[DD];
    __shared__ float sh_lo[DD];
    __shared__ double partd[32 * PAD];
    int b = blockIdx.x >> 4;
    int r0 = (blockIdx.x & 15) * 32;
    for (int i = threadIdx.x; i < DD; i += blockDim.x) {
        double h = g_hs[b * DD + i];
        float hi = (float)h;
        sh_hi[i] = hi;
        sh_lo[i] = (float)(h - (double)hi);
    }
    __syncthreads();

    int warp = threadIdx.x >> 5, lane = threadIdx.x & 31;
#pragma unroll
    for (int t = 0; t < 4; t++) {
        int r = warp * 4 + t;
        const float4* wr = (const float4*)(Wk + (size_t)(r0 + r) * DD);
        float4 x0 = wr[lane];
        float4 x1 = wr[lane + 32];
        float4 x2 = wr[lane + 64];
        float4 x3 = wr[lane + 96];
        float s0 = 0.f, s1 = 0.f, s2 = 0.f, s3 = 0.f;
        float c0 = 0.f, c1 = 0.f, c2 = 0.f, c3 = 0.f;
        int ca = 4 * lane, cb = 4 * (lane + 32), cc = 4 * (lane + 64), cd = 4 * (lane + 96);
        df_acc(x0.x, sh_hi[ca + 0], sh_lo[ca + 0], s0, c0);
        df_acc(x0.y, sh_hi[ca + 1], sh_lo[ca + 1], s1, c1);
        df_acc(x0.z, sh_hi[ca + 2], sh_lo[ca + 2], s2, c2);
        df_acc(x0.w, sh_hi[ca + 3], sh_lo[ca + 3], s3, c3);
        df_acc(x1.x, sh_hi[cb + 0], sh_lo[cb + 0], s0, c0);
        df_acc(x1.y, sh_hi[cb + 1], sh_lo[cb + 1], s1, c1);
        df_acc(x1.z, sh_hi[cb + 2], sh_lo[cb + 2], s2, c2);
        df_acc(x1.w, sh_hi[cb + 3], sh_lo[cb + 3], s3, c3);
        df_acc(x2.x, sh_hi[cc + 0], sh_lo[cc + 0], s0, c0);
        df_acc(x2.y, sh_hi[cc + 1], sh_lo[cc + 1], s1, c1);
        df_acc(x2.z, sh_hi[cc + 2], sh_lo[cc + 2], s2, c2);
        df_acc(x2.w, sh_hi[cc + 3], sh_lo[cc + 3], s3, c3);
        df_acc(x3.x, sh_hi[cd + 0], sh_lo[cd + 0], s0, c0);
        df_acc(x3.y, sh_hi[cd + 1], sh_lo[cd + 1], s1, c1);
        df_acc(x3.z, sh_hi[cd + 2], sh_lo[cd + 2], s2, c2);
        df_acc(x3.w, sh_hi[cd + 3], sh_lo[cd + 3], s3, c3);
        partd[r * PAD + lane] = (((double)s0 + (double)c0) + ((double)s1 + (double)c1))
                              + (((double)s2 + (double)c2) + ((double)s3 + (double)c3));
    }
    __syncwarp();
    if (lane < 4) {
        int r = warp * 4 + lane;
        const double* p = &partd[r * PAD];
        double q[16];
#pragma unroll
        for (int j = 0; j < 16; j++) q[j] = p[j] + p[j + 16];
#pragma unroll
        for (int w = 8; w > 0; w >>= 1)
#pragma unroll
            for (int j = 0; j < 16; j++) if (j < w) q[j] = q[j] + q[j + w];
        g_t[b * DD + r0 + r] = q[0];
    }
}

// ---------------- kernel 3b: vpart (df64, fp32 pipes) --------------------------
__global__ void __launch_bounds__(512, 2) matvec2_kernel(const float* __restrict__ Wq) {
    __shared__ float sh_hi[64];
    __shared__ float sh_lo[64];
    int b = blockIdx.x >> 3;
    int chunk = blockIdx.x & 7;
    int d0 = chunk * 64;
    if (threadIdx.x < 64) {
        double h = g_t[b * DD + d0 + threadIdx.x];
        float hi = (float)h;
        sh_hi[threadIdx.x] = hi;
        sh_lo[threadIdx.x] = (float)(h - (double)hi);
    }
    __syncthreads();

    int e = threadIdx.x;
    const float* wp = Wq + (size_t)d0 * DD + e;
    float s0 = 0.f, s1 = 0.f, s2 = 0.f, s3 = 0.f;
    float c0 = 0.f, c1 = 0.f, c2 = 0.f, c3 = 0.f;
#pragma unroll 4
    for (int d = 0; d < 64; d += 4) {
        float w0 = wp[(size_t)(d + 0) * DD];
        float w1 = wp[(size_t)(d + 1) * DD];
        float w2 = wp[(size_t)(d + 2) * DD];
        float w3 = wp[(size_t)(d + 3) * DD];
        df_acc(w0, sh_hi[d + 0], sh_lo[d + 0], s0, c0);
        df_acc(w1, sh_hi[d + 1], sh_lo[d + 1], s1, c1);
        df_acc(w2, sh_hi[d + 2], sh_lo[d + 2], s2, c2);
        df_acc(w3, sh_hi[d + 3], sh_lo[d + 3], s3, c3);
    }
    double r = (((double)s0 + (double)c0) + ((double)s1 + (double)c1))
             + (((double)s2 + (double)c2) + ((double)s3 + (double)c3));
    g_vpart[((size_t)b * 8 + chunk) * DD + e] = r;
}

// ---------------- kernel 3c: combine partials -> g_v (fixed order) ------------
__global__ void matvec3_kernel() {
    int b = blockIdx.x;
    int e = threadIdx.x;
    double s = 0.0;
#pragma unroll
    for (int c = 0; c < 8; c++) s += g_vpart[((size_t)b * 8 + c) * DD + e];
    g_v[b * DD + e] = (float)s;
}

// ---------------- kernel 4: scores + hard bits (stream + warp-local reduce) ---
__global__ void __launch_bounds__(256, 4) scores_kernel(const float* __restrict__ hidden,
                                                        const float* __restrict__ noise) {
    __shared__ float part[128 * PAD];
    __shared__ float sh_v[DD];
    int warp = threadIdx.x >> 5;
    int lane = threadIdx.x & 31;
    int batch = blockIdx.x >> 6;
    int tok0  = ((blockIdx.x & 63) * 8 + warp) * 16;

    for (int i = threadIdx.x; i < DD; i += blockDim.x) sh_v[i] = g_v[batch * DD + i];
    __syncthreads();

    const float4* vv = (const float4*)sh_v;
    float4 w0 = vv[lane], w1 = vv[lane + 32], w2 = vv[lane + 64], w3 = vv[lane + 96];

    const float4* base = (const float4*)(hidden + (size_t)batch * SS * DD);
#pragma unroll
    for (int t = 0; t < 16; t += 2) {
#pragma unroll
        for (int i = 0; i < 2; i++) {
            const float4* row = base + (size_t)(tok0 + t + i) * (DD / 4);
            float4 x0 = row[lane];
            float4 x1 = row[lane + 32];
            float4 x2 = row[lane + 64];
            float4 x3 = row[lane + 96];
            float s0 = 0.f, s1 = 0.f, s2 = 0.f, s3 = 0.f;
            s0 = fmaf(x0.x, w0.x, s0); s1 = fmaf(x0.y, w0.y, s1);
            s2 = fmaf(x0.z, w0.z, s2); s3 = fmaf(x0.w, w0.w, s3);
            s0 = fmaf(x1.x, w1.x, s0); s1 = fmaf(x1.y, w1.y, s1);
            s2 = fmaf(x1.z, w1.z, s2); s3 = fmaf(x1.w, w1.w, s3);
            s0 = fmaf(x2.x, w2.x, s0); s1 = fmaf(x2.y, w2.y, s1);
            s2 = fmaf(x2.z, w2.z, s2); s3 = fmaf(x2.w, w2.w, s3);
            s0 = fmaf(x3.x, w3.x, s0); s1 = fmaf(x3.y, w3.y, s1);
            s2 = fmaf(x3.z, w3.z, s2); s3 = fmaf(x3.w, w3.w, s3);
            part[(warp * 16 + t + i) * PAD + lane] = (s0 + s1) + (s2 + s3);
        }
    }
    __syncwarp();
    if (lane < 16) {
        int r = warp * 16 + lane;
        const float* p = &part[r * PAD];
        double q[16];
#pragma unroll
        for (int j = 0; j < 16; j++) q[j] = (double)p[j] + (double)p[j + 16];
#pragma unroll
        for (int w = 8; w > 0; w >>= 1)
#pragma unroll
            for (int j = 0; j < 16; j++) if (j < w) q[j] = q[j] + q[j + w];
        int g = batch * SS + tok0 + lane;
        double score = SCALE_F * (double)g_invnorm[g] * q[0];
        float nz = noise[g];
        double logistic = (double)logf(nz) - (double)log1pf(-nz);
        g_hard[g] = (score + logistic > 0.0) ? 1 : 0;
    }
}

// ---------------- kernel 5: per-batch stable compaction scan ------------------
__global__ void scan_kernel() {
    int b = blockIdx.x;
    int tid = threadIdx.x;
    const int TPT = SS / 1024;  // 8
    int base = b * SS + tid * TPT;

    int loc[TPT];
    int cnt = 0;
#pragma unroll
    for (int i = 0; i < TPT; i++) { loc[i] = g_hard[base + i]; cnt += loc[i]; }

    int lane = tid & 31, warp = tid >> 5;
    int v = cnt;
#pragma unroll
    for (int o = 1; o < 32; o <<= 1) {
        int n = __shfl_up_sync(0xffffffffu, v, o);
        if (lane >= o) v += n;
    }
    __shared__ int wsum[32];
    if (lane == 31) wsum[warp] = v;
    __syncthreads();
    if (warp == 0) {
        int w = wsum[lane];
#pragma unroll
        for (int o = 1; o < 32; o <<= 1) {
            int n = __shfl_up_sync(0xffffffffu, w, o);
            if (lane >= o) w += n;
        }
        wsum[lane] = w;
    }
    __syncthreads();
    int excl = (v - cnt) + (warp > 0 ? wsum[warp - 1] : 0);

    int pos = excl;
#pragma unroll
    for (int i = 0; i < TPT; i++)
        if (loc[i]) g_keptidx[b * SS + (pos++)] = tid * TPT + i;
    if (tid == 1023) g_count[b] = excl + cnt;
}

// ---------------- kernel 6: write pooled (gather kept rows, zero the rest) ----
__global__ void __launch_bounds__(256, 4) writeout_kernel(const float* __restrict__ hidden,
                                                          float* __restrict__ out) {
    int wg = blockIdx.x * (blockDim.x >> 5) + (threadIdx.x >> 5);
    int lane = threadIdx.x & 31;
    int b = wg >> 12;          // 4096 warps per batch (2 rows each)
    int i0 = (wg & 4095) * 2;
    int cnt = g_count[b];

    bool v0 = i0 < cnt, v1 = (i0 + 1) < cnt;
    int s0 = v0 ? g_keptidx[b * SS + i0] : 0;
    int s1 = v1 ? g_keptidx[b * SS + i0 + 1] : 0;
    float inv0 = v0 ? g_invnorm[b * SS + s0] : 0.f;
    float inv1 = v1 ? g_invnorm[b * SS + s1] : 0.f;

    const float4* r0 = (const float4*)hidden + ((size_t)b * SS + s0) * (DD / 4);
    const float4* r1 = (const float4*)hidden + ((size_t)b * SS + s1) * (DD / 4);
    float4 a[4], c[4];
    float4 z = make_float4(0.f, 0.f, 0.f, 0.f);
#pragma unroll
    for (int k = 0; k < 4; k++) a[k] = v0 ? r0[lane + 32 * k] : z;
#pragma unroll
    for (int k = 0; k < 4; k++) c[k] = v1 ? r1[lane + 32 * k] : z;

    float4* o0 = (float4*)out + ((size_t)b * SS + i0) * (DD / 4);
    float4* o1 = o0 + (DD / 4);
#pragma unroll
    for (int k = 0; k < 4; k++) {
        float4 x = a[k];
        x.x *= inv0; x.y *= inv0; x.z *= inv0; x.w *= inv0;
        o0[lane + 32 * k] = x;
    }
#pragma unroll
    for (int k = 0; k < 4; k++) {
        float4 x = c[k];
        x.x *= inv1; x.y *= inv1; x.z *= inv1; x.w *= inv1;
        o1[lane + 32 * k] = x;
    }
}

// ---------------- kernel 7: binomial loss -> tail of output -------------------
__global__ void loss_kernel(float* __restrict__ out, long long out_size) {
    __shared__ double sh[BB];
    __shared__ float sh_loss;
    int tid = threadIdx.x;
    if (tid < BB) {
        double k = (double)g_count[tid];
        double n = (double)SS;
        double lp = lgamma(n + 1.0) - lgamma(k + 1.0) - lgamma(n - k + 1.0)
                  + k * log(0.2) + (n - k) * log1p(-0.2);
        sh[tid] = lp;
    }
    __syncthreads();
    if (tid == 0) {
        double m = 0.0;
        for (int b = 0; b < BB; b++) m += sh[b];
        m /= (double)BB;
        sh_loss = (float)(-m / (double)SS);
    }
    __syncthreads();
    long long start = (long long)BB * SS * DD;
    for (long long i = start + tid; i < out_size; i += blockDim.x) out[i] = sh_loss;
}

// ---------------- launch ------------------------------------------------------
extern "C" void kernel_launch(void* const* d_in, const int* in_sizes, int n_in,
                              void* d_out, int out_size) {
    const float* hidden = (const float*)d_in[0];
    const float* Wq     = (const float*)d_in[1];
    const float* Wk     = (const float*)d_in[2];
    const float* noise  = (const float*)d_in[3];
    float* out = (float*)d_out;

    zero_hs_kernel<<<(BB * DD + 511) / 512, 512>>>();
    normhs_kernel<<<1024, 256>>>(hidden);
    matvec1_kernel<<<BB * 16, 256>>>(Wk);
    matvec2_kernel<<<BB * 8, 512>>>(Wq);
    matvec3_kernel<<<BB, DD>>>();
    scores_kernel<<<1024, 256>>>(hidden, noise);
    scan_kernel<<<BB, 1024>>>();
    writeout_kernel<<<(BB * SS) / 16, 256>>>(hidden, out);
    loss_kernel<<<1, 256>>>(out, (long long)out_size);
}